// round 14
// baseline (speedup 1.0000x reference)
#include <cuda_runtime.h>
#include <cuda_bf16.h>
#include <cstdint>

// Spatially-varying 19x19 blur.
// out[b,c,i,j] = (1/361) * sum_{u,v} x_reflectpad[b,c,i+u-9,j+v-9] * kernel[b,u*19+v,i,j]
//
// B=2, C=3, H=W=256, L=19, K2=361. Kernel tensor (189 MB) read exactly once.
// R14 = R13's full-row demand batch with a REAL register budget:
// 256 thr/block, launch_bounds(256,2) -> 128 regs/thread, so kv[19] float4
// (76 regs of in-flight LDG.128) actually materializes (R13's 512-thr config
// silently capped at 64 regs and re-split the batch).
// Each warp = one 128-px row -> 512B contiguous per tap. NGRP=4 tap split.

#define LK    19
#define PADR  9
#define HGT   256
#define WID   256
#define HW    (HGT * WID)
#define K2    (LK * LK)

#define TJ    128
#define TI    2
#define PGRP  64      // pixel-group: 32 j-threads x 2 rows, 4 px each
#define NGRP  4       // tap groups
#define NTHR  (PGRP * NGRP)      // 256
#define PCOLS (TJ + LK - 1)      // 146
#define PROWS (TI + LK - 1)      // 20
#define PITCH 148                // 16B-aligned float4 rows

#define PATCH_FLOATS (3 * PROWS * PITCH)        // 8880
#define PART_FLOATS  ((NGRP - 1) * PGRP * 13)   // 2496
#define SMEM_BYTES   ((PATCH_FLOATS + PART_FLOATS) * 4)   // 45504

__global__ __launch_bounds__(NTHR, 2)
void svblur_kernel(const float* __restrict__ x,
                   const float* __restrict__ kern,
                   float* __restrict__ out)
{
    extern __shared__ float dsm[];
    float* patch = dsm;                    // [3][PROWS][PITCH]
    float* part  = dsm + PATCH_FLOATS;     // [NGRP-1][PGRP][13]

    const int tid = threadIdx.x;
    const int jt  = blockIdx.x;   // 0..1
    const int ip  = blockIdx.y;   // 0..127
    const int b   = blockIdx.z;   // 0..1
    const int j0  = jt * TJ;
    const int i0  = ip * TI;

    // ---- stage input patch (reflect padding), all 3 channels ----
    const float* xb = x + (size_t)b * 3 * HW;
    for (int e = tid; e < PROWS * PCOLS; e += NTHR) {
        int pr = e / PCOLS;
        int pc = e - pr * PCOLS;
        int gi = i0 - PADR + pr;
        int gj = j0 - PADR + pc;
        gi = (gi < 0) ? -gi : ((gi >= HGT) ? 2 * (HGT - 1) - gi : gi);
        gj = (gj < 0) ? -gj : ((gj >= WID) ? 2 * (WID - 1) - gj : gj);
        const float* src = xb + gi * WID + gj;
        patch[(0 * PROWS + pr) * PITCH + pc] = src[0 * HW];
        patch[(1 * PROWS + pr) * PITCH + pc] = src[1 * HW];
        patch[(2 * PROWS + pr) * PITCH + pc] = src[2 * HW];
    }
    __syncthreads();

    const int g    = tid >> 6;             // tap group 0..3
    const int tid2 = tid & (PGRP - 1);     // 0..63
    const int jthr = tid2 & 31;            // 0..31
    const int ir   = tid2 >> 5;            // 0..1
    const int i    = i0 + ir;
    const int jj   = jthr * 4;             // local j of first of 4 px

    const int u_lo = (g * LK) / NGRP;          // 0,4,9,14
    const int u_hi = ((g + 1) * LK) / NGRP;    // 4,9,14,19

    const float4* kp = (const float4*)(kern + (size_t)b * K2 * HW
                                            + (size_t)i * WID + j0 + jj);

    float a0[4] = {0.f, 0.f, 0.f, 0.f};
    float a1[4] = {0.f, 0.f, 0.f, 0.f};
    float a2[4] = {0.f, 0.f, 0.f, 0.f};

    #pragma unroll 1
    for (int u = u_lo; u < u_hi; u++) {
        const float4* kru = kp + (size_t)u * LK * (HW / 4);

        // ---- full-row demand batch: 19 independent LDG.128 before any use ----
        float4 kv[LK];
        #pragma unroll
        for (int v = 0; v < LK; v++) {
            kv[v] = __ldg(kru + (size_t)v * (HW / 4));
        }

        const float4* r0 = (const float4*)&patch[(0 * PROWS + ir + u) * PITCH];
        const float4* r1 = (const float4*)&patch[(1 * PROWS + ir + u) * PITCH];
        const float4* r2 = (const float4*)&patch[(2 * PROWS + ir + u) * PITCH];
        const int jb = jthr;

        #pragma unroll
        for (int vb = 0; vb < 5; vb++) {          // v chunks: 4,4,4,4,3
            const int vmax = (vb == 4) ? 3 : 4;
            float4 lo0 = r0[jb + vb], hi0 = r0[jb + vb + 1];
            float4 lo1 = r1[jb + vb], hi1 = r1[jb + vb + 1];
            float4 lo2 = r2[jb + vb], hi2 = r2[jb + vb + 1];
            float w0[8] = {lo0.x, lo0.y, lo0.z, lo0.w, hi0.x, hi0.y, hi0.z, hi0.w};
            float w1[8] = {lo1.x, lo1.y, lo1.z, lo1.w, hi1.x, hi1.y, hi1.z, hi1.w};
            float w2[8] = {lo2.x, lo2.y, lo2.z, lo2.w, hi2.x, hi2.y, hi2.z, hi2.w};

            #pragma unroll
            for (int s = 0; s < 4; s++) {
                if (s >= vmax) break;
                const float4 k4 = kv[vb * 4 + s];
                a0[0] += w0[s + 0] * k4.x;  a0[1] += w0[s + 1] * k4.y;
                a0[2] += w0[s + 2] * k4.z;  a0[3] += w0[s + 3] * k4.w;
                a1[0] += w1[s + 0] * k4.x;  a1[1] += w1[s + 1] * k4.y;
                a1[2] += w1[s + 2] * k4.z;  a1[3] += w1[s + 3] * k4.w;
                a2[0] += w2[s + 0] * k4.x;  a2[1] += w2[s + 1] * k4.y;
                a2[2] += w2[s + 2] * k4.z;  a2[3] += w2[s + 3] * k4.w;
            }
        }
    }

    // ---- combine the 4 tap-groups ----
    if (g > 0) {
        float* p = part + ((g - 1) * PGRP + tid2) * 13;
        #pragma unroll
        for (int t = 0; t < 4; t++) { p[t] = a0[t]; p[4 + t] = a1[t]; p[8 + t] = a2[t]; }
    }
    __syncthreads();
    if (g == 0) {
        #pragma unroll
        for (int q = 0; q < NGRP - 1; q++) {
            const float* p = part + (q * PGRP + tid2) * 13;
            #pragma unroll
            for (int t = 0; t < 4; t++) {
                a0[t] += p[t]; a1[t] += p[4 + t]; a2[t] += p[8 + t];
            }
        }
        const float inv = 1.0f / (float)K2;
        float* ob = out + (size_t)b * 3 * HW + (size_t)i * WID + j0 + jj;
        float4 o0 = make_float4(a0[0]*inv, a0[1]*inv, a0[2]*inv, a0[3]*inv);
        float4 o1 = make_float4(a1[0]*inv, a1[1]*inv, a1[2]*inv, a1[3]*inv);
        float4 o2 = make_float4(a2[0]*inv, a2[1]*inv, a2[2]*inv, a2[3]*inv);
        *(float4*)(ob + 0 * HW) = o0;
        *(float4*)(ob + 1 * HW) = o1;
        *(float4*)(ob + 2 * HW) = o2;
    }
}

extern "C" void kernel_launch(void* const* d_in, const int* in_sizes, int n_in,
                              void* d_out, int out_size)
{
    const float* x    = (const float*)d_in[0];
    const float* kern = (const float*)d_in[1];
    // defensive: identify tensors by size (input = 393216, kernel = 47316992)
    if (n_in >= 2 && in_sizes[0] > in_sizes[1]) {
        const float* t = x; x = kern; kern = t;
    }

    cudaFuncSetAttribute(svblur_kernel,
                         cudaFuncAttributeMaxDynamicSharedMemorySize, SMEM_BYTES);

    dim3 grid(WID / TJ, HGT / TI, 2);   // (2, 128, 2) = 512 blocks, 8 warps
    svblur_kernel<<<grid, NTHR, SMEM_BYTES>>>(x, kern, (float*)d_out);
}

// round 16
// speedup vs baseline: 1.0238x; 1.0238x over previous
#include <cuda_runtime.h>
#include <cuda_bf16.h>
#include <cstdint>

// Spatially-varying 19x19 blur.
// out[b,c,i,j] = (1/361) * sum_{u,v} x_reflectpad[b,c,i+u-9,j+v-9] * kernel[b,u*19+v,i,j]
//
// B=2, C=3, H=W=256, L=19, K2=361. Kernel tensor (189 MB) read exactly once.
// R16 = R15 resubmit (R15 bench was an infra flake; kernel has no hang-capable
// constructs). R13's per-thread schedule with BALANCED residency:
// TJ=128, 256 thr, launch_bounds(256,4) -> 64-reg regime, static smem 45.5KB
// -> 4 blocks/SM, 512 blocks in ONE fully-resident wave (R13: 256 blocks at
// 2/SM left 40 of 148 SMs half-idle -> 86.5% spatial utilization).

#define LK    19
#define PADR  9
#define HGT   256
#define WID   256
#define HW    (HGT * WID)
#define K2    (LK * LK)

#define TJ    128
#define TI    2
#define PGRP  64      // pixel-group: 32 j-threads x 2 rows, 4 px each
#define NGRP  4       // tap groups
#define NTHR  (PGRP * NGRP)      // 256
#define PCOLS (TJ + LK - 1)      // 146
#define PROWS (TI + LK - 1)      // 20
#define PITCH 148                // 16B-aligned float4 rows

__global__ __launch_bounds__(NTHR, 4)
void svblur_kernel(const float* __restrict__ x,
                   const float* __restrict__ kern,
                   float* __restrict__ out)
{
    __shared__ float patch[3 * PROWS * PITCH];     // 35520 B
    __shared__ float part[(NGRP - 1) * PGRP * 13]; // 9984 B -> total 45504 B

    const int tid = threadIdx.x;
    const int jt  = blockIdx.x;   // 0..1
    const int ip  = blockIdx.y;   // 0..127
    const int b   = blockIdx.z;   // 0..1
    const int j0  = jt * TJ;
    const int i0  = ip * TI;

    // ---- stage input patch (reflect padding), all 3 channels ----
    const float* xb = x + (size_t)b * 3 * HW;
    for (int e = tid; e < PROWS * PCOLS; e += NTHR) {
        int pr = e / PCOLS;
        int pc = e - pr * PCOLS;
        int gi = i0 - PADR + pr;
        int gj = j0 - PADR + pc;
        gi = (gi < 0) ? -gi : ((gi >= HGT) ? 2 * (HGT - 1) - gi : gi);
        gj = (gj < 0) ? -gj : ((gj >= WID) ? 2 * (WID - 1) - gj : gj);
        const float* src = xb + gi * WID + gj;
        patch[(0 * PROWS + pr) * PITCH + pc] = src[0 * HW];
        patch[(1 * PROWS + pr) * PITCH + pc] = src[1 * HW];
        patch[(2 * PROWS + pr) * PITCH + pc] = src[2 * HW];
    }
    __syncthreads();

    const int g    = tid >> 6;             // tap group 0..3
    const int tid2 = tid & (PGRP - 1);     // 0..63
    const int jthr = tid2 & 31;            // 0..31
    const int ir   = tid2 >> 5;            // 0..1
    const int i    = i0 + ir;
    const int jj   = jthr * 4;             // local j of first of 4 px

    const int u_lo = (g * LK) / NGRP;          // 0,4,9,14
    const int u_hi = ((g + 1) * LK) / NGRP;    // 4,9,14,19

    const float4* kp = (const float4*)(kern + (size_t)b * K2 * HW
                                            + (size_t)i * WID + j0 + jj);

    float a0[4] = {0.f, 0.f, 0.f, 0.f};
    float a1[4] = {0.f, 0.f, 0.f, 0.f};
    float a2[4] = {0.f, 0.f, 0.f, 0.f};

    #pragma unroll 1
    for (int u = u_lo; u < u_hi; u++) {
        const float4* kru = kp + (size_t)u * LK * (HW / 4);

        // full-row batch in source; ptxas re-chunks to fit 64 regs (R13 regime)
        float4 kv[LK];
        #pragma unroll
        for (int v = 0; v < LK; v++) {
            kv[v] = __ldg(kru + (size_t)v * (HW / 4));
        }

        const float4* r0 = (const float4*)&patch[(0 * PROWS + ir + u) * PITCH];
        const float4* r1 = (const float4*)&patch[(1 * PROWS + ir + u) * PITCH];
        const float4* r2 = (const float4*)&patch[(2 * PROWS + ir + u) * PITCH];
        const int jb = jthr;

        #pragma unroll
        for (int vb = 0; vb < 5; vb++) {          // v chunks: 4,4,4,4,3
            const int vmax = (vb == 4) ? 3 : 4;
            float4 lo0 = r0[jb + vb], hi0 = r0[jb + vb + 1];
            float4 lo1 = r1[jb + vb], hi1 = r1[jb + vb + 1];
            float4 lo2 = r2[jb + vb], hi2 = r2[jb + vb + 1];
            float w0[8] = {lo0.x, lo0.y, lo0.z, lo0.w, hi0.x, hi0.y, hi0.z, hi0.w};
            float w1[8] = {lo1.x, lo1.y, lo1.z, lo1.w, hi1.x, hi1.y, hi1.z, hi1.w};
            float w2[8] = {lo2.x, lo2.y, lo2.z, lo2.w, hi2.x, hi2.y, hi2.z, hi2.w};

            #pragma unroll
            for (int s = 0; s < 4; s++) {
                if (s >= vmax) break;
                const float4 k4 = kv[vb * 4 + s];
                a0[0] += w0[s + 0] * k4.x;  a0[1] += w0[s + 1] * k4.y;
                a0[2] += w0[s + 2] * k4.z;  a0[3] += w0[s + 3] * k4.w;
                a1[0] += w1[s + 0] * k4.x;  a1[1] += w1[s + 1] * k4.y;
                a1[2] += w1[s + 2] * k4.z;  a1[3] += w1[s + 3] * k4.w;
                a2[0] += w2[s + 0] * k4.x;  a2[1] += w2[s + 1] * k4.y;
                a2[2] += w2[s + 2] * k4.z;  a2[3] += w2[s + 3] * k4.w;
            }
        }
    }

    // ---- combine the 4 tap-groups ----
    if (g > 0) {
        float* p = part + ((g - 1) * PGRP + tid2) * 13;
        #pragma unroll
        for (int t = 0; t < 4; t++) { p[t] = a0[t]; p[4 + t] = a1[t]; p[8 + t] = a2[t]; }
    }
    __syncthreads();
    if (g == 0) {
        #pragma unroll
        for (int q = 0; q < NGRP - 1; q++) {
            const float* p = part + (q * PGRP + tid2) * 13;
            #pragma unroll
            for (int t = 0; t < 4; t++) {
                a0[t] += p[t]; a1[t] += p[4 + t]; a2[t] += p[8 + t];
            }
        }
        const float inv = 1.0f / (float)K2;
        float* ob = out + (size_t)b * 3 * HW + (size_t)i * WID + j0 + jj;
        float4 o0 = make_float4(a0[0]*inv, a0[1]*inv, a0[2]*inv, a0[3]*inv);
        float4 o1 = make_float4(a1[0]*inv, a1[1]*inv, a1[2]*inv, a1[3]*inv);
        float4 o2 = make_float4(a2[0]*inv, a2[1]*inv, a2[2]*inv, a2[3]*inv);
        *(float4*)(ob + 0 * HW) = o0;
        *(float4*)(ob + 1 * HW) = o1;
        *(float4*)(ob + 2 * HW) = o2;
    }
}

extern "C" void kernel_launch(void* const* d_in, const int* in_sizes, int n_in,
                              void* d_out, int out_size)
{
    const float* x    = (const float*)d_in[0];
    const float* kern = (const float*)d_in[1];
    // defensive: identify tensors by size (input = 393216, kernel = 47316992)
    if (n_in >= 2 && in_sizes[0] > in_sizes[1]) {
        const float* t = x; x = kern; kern = t;
    }

    dim3 grid(WID / TJ, HGT / TI, 2);   // (2, 128, 2) = 512 blocks, 8 warps
    svblur_kernel<<<grid, NTHR>>>(x, kern, (float*)d_out);
}

// round 17
// speedup vs baseline: 1.2683x; 1.2388x over previous
#include <cuda_runtime.h>
#include <cuda_bf16.h>
#include <cstdint>

// Spatially-varying 19x19 blur.
// out[b,c,i,j] = (1/361) * sum_{u,v} x_reflectpad[b,c,i+u-9,j+v-9] * kernel[b,u*19+v,i,j]
//
// B=2, C=3, H=W=256, L=19, K2=361. Kernel tensor (189 MB) read exactly once.
// R17 = R13 (best: 36.06us ncu, DRAM 68.3%, clean 195MB) + cache-hygiene prefetch:
//  - demand loads via __ldcs (evict-first): consumed streaming lines leave L2
//    immediately instead of evicting not-yet-consumed prefetched lines
//  - R12's cheap per-u-row prefetch placement (alu stayed ~7.6% there), strictly
//    within-group rows -> duplicate-free at issue; prologue = first row only

#define LK    19
#define PADR  9
#define HGT   256
#define WID   256
#define HW    (HGT * WID)
#define K2    (LK * LK)

#define TJ    256     // full row
#define TI    2
#define PGRP  128     // pixel-group threads: 64 j-threads x 2 rows, 4 px each
#define NGRP  4       // tap groups
#define NTHR  (PGRP * NGRP)      // 512
#define PCOLS (TJ + LK - 1)      // 274
#define PROWS (TI + LK - 1)      // 20
#define PITCH 276                // 16B-aligned float4 rows

#define TAPB  (TI * WID * 4)     // 2048 bytes per tap
#define LINES_PER_ROW (LK * (TAPB / 128))   // 19*16 = 304

#define PATCH_FLOATS (3 * PROWS * PITCH)        // 16560
#define PART_FLOATS  ((NGRP - 1) * PGRP * 13)   // 4992
#define SMEM_BYTES   ((PATCH_FLOATS + PART_FLOATS) * 4)   // 86208

__device__ __forceinline__ void pf_l2(const void* p) {
    asm volatile("prefetch.global.L2 [%0];" :: "l"(p));
}

// prefetch all 19 taps of u-row 'u' (block-level 2KB spans), spread over group
__device__ __forceinline__ void prefetch_row(const char* pfb, int u, int tid2) {
    const size_t row_off = (size_t)u * LK * HW * 4;
    #pragma unroll
    for (int e = tid2; e < LINES_PER_ROW; e += PGRP) {
        const int v = e >> 4;          // tap within row
        const int l = e & 15;          // 128B line within 2KB tap span
        pf_l2(pfb + row_off + (size_t)v * HW * 4 + l * 128);
    }
}

__global__ __launch_bounds__(NTHR, 2)
void svblur_kernel(const float* __restrict__ x,
                   const float* __restrict__ kern,
                   float* __restrict__ out)
{
    extern __shared__ float dsm[];
    float* patch = dsm;                    // [3][PROWS][PITCH]
    float* part  = dsm + PATCH_FLOATS;     // [NGRP-1][PGRP][13]

    const int tid = threadIdx.x;
    const int ip  = blockIdx.x;   // 0..127 : i-pair
    const int b   = blockIdx.y;   // 0..1
    const int i0  = ip * TI;

    const int g    = tid >> 7;             // tap group 0..3
    const int tid2 = tid & (PGRP - 1);     // 0..127
    const int u_lo = (g * LK) / NGRP;          // 0,4,9,14
    const int u_hi = ((g + 1) * LK) / NGRP;    // 4,9,14,19

    // block-level prefetch base: kern[b][.][i0..i0+1][:]
    const char* pfb = (const char*)(kern + (size_t)b * K2 * HW + (size_t)i0 * WID);

    // ---- prologue prefetch: first row of this group only ----
    prefetch_row(pfb, u_lo, tid2);

    // ---- stage input patch (reflect padding), all 3 channels ----
    const float* xb = x + (size_t)b * 3 * HW;
    for (int e = tid; e < PROWS * PCOLS; e += NTHR) {
        int pr = e / PCOLS;
        int pc = e - pr * PCOLS;
        int gi = i0 - PADR + pr;
        int gj = -PADR + pc;
        gi = (gi < 0) ? -gi : ((gi >= HGT) ? 2 * (HGT - 1) - gi : gi);
        gj = (gj < 0) ? -gj : ((gj >= WID) ? 2 * (WID - 1) - gj : gj);
        const float* src = xb + gi * WID + gj;
        patch[(0 * PROWS + pr) * PITCH + pc] = src[0 * HW];
        patch[(1 * PROWS + pr) * PITCH + pc] = src[1 * HW];
        patch[(2 * PROWS + pr) * PITCH + pc] = src[2 * HW];
    }
    __syncthreads();

    const int jthr = tid2 & 63;            // 0..63
    const int ir   = tid2 >> 6;            // 0..1
    const int i    = i0 + ir;
    const int jj   = jthr * 4;             // local j of first of 4 px

    const float4* kp = (const float4*)(kern + (size_t)b * K2 * HW
                                            + (size_t)i * WID + jj);

    float a0[4] = {0.f, 0.f, 0.f, 0.f};
    float a1[4] = {0.f, 0.f, 0.f, 0.f};
    float a2[4] = {0.f, 0.f, 0.f, 0.f};

    #pragma unroll 1
    for (int u = u_lo; u < u_hi; u++) {
        // prefetch next row of THIS group's range (once per row; cheap placement)
        if (u + 1 < u_hi) prefetch_row(pfb, u + 1, tid2);

        const float4* kru = kp + (size_t)u * LK * (HW / 4);

        // full-row batch in source; ptxas re-chunks under the 64-reg budget
        float4 kv[LK];
        #pragma unroll
        for (int v = 0; v < LK; v++) {
            kv[v] = __ldcs(kru + (size_t)v * (HW / 4));   // evict-first streaming
        }

        const float4* r0 = (const float4*)&patch[(0 * PROWS + ir + u) * PITCH];
        const float4* r1 = (const float4*)&patch[(1 * PROWS + ir + u) * PITCH];
        const float4* r2 = (const float4*)&patch[(2 * PROWS + ir + u) * PITCH];
        const int jb = jthr;

        #pragma unroll
        for (int vb = 0; vb < 5; vb++) {          // v chunks: 4,4,4,4,3
            const int vmax = (vb == 4) ? 3 : 4;
            float4 lo0 = r0[jb + vb], hi0 = r0[jb + vb + 1];
            float4 lo1 = r1[jb + vb], hi1 = r1[jb + vb + 1];
            float4 lo2 = r2[jb + vb], hi2 = r2[jb + vb + 1];
            float w0[8] = {lo0.x, lo0.y, lo0.z, lo0.w, hi0.x, hi0.y, hi0.z, hi0.w};
            float w1[8] = {lo1.x, lo1.y, lo1.z, lo1.w, hi1.x, hi1.y, hi1.z, hi1.w};
            float w2[8] = {lo2.x, lo2.y, lo2.z, lo2.w, hi2.x, hi2.y, hi2.z, hi2.w};

            #pragma unroll
            for (int s = 0; s < 4; s++) {
                if (s >= vmax) break;
                const float4 k4 = kv[vb * 4 + s];
                a0[0] += w0[s + 0] * k4.x;  a0[1] += w0[s + 1] * k4.y;
                a0[2] += w0[s + 2] * k4.z;  a0[3] += w0[s + 3] * k4.w;
                a1[0] += w1[s + 0] * k4.x;  a1[1] += w1[s + 1] * k4.y;
                a1[2] += w1[s + 2] * k4.z;  a1[3] += w1[s + 3] * k4.w;
                a2[0] += w2[s + 0] * k4.x;  a2[1] += w2[s + 1] * k4.y;
                a2[2] += w2[s + 2] * k4.z;  a2[3] += w2[s + 3] * k4.w;
            }
        }
    }

    // ---- combine the 4 tap-groups ----
    if (g > 0) {
        float* p = part + ((g - 1) * PGRP + tid2) * 13;
        #pragma unroll
        for (int t = 0; t < 4; t++) { p[t] = a0[t]; p[4 + t] = a1[t]; p[8 + t] = a2[t]; }
    }
    __syncthreads();
    if (g == 0) {
        #pragma unroll
        for (int q = 0; q < NGRP - 1; q++) {
            const float* p = part + (q * PGRP + tid2) * 13;
            #pragma unroll
            for (int t = 0; t < 4; t++) {
                a0[t] += p[t]; a1[t] += p[4 + t]; a2[t] += p[8 + t];
            }
        }
        const float inv = 1.0f / (float)K2;
        float* ob = out + (size_t)b * 3 * HW + (size_t)i * WID + jj;
        float4 o0 = make_float4(a0[0]*inv, a0[1]*inv, a0[2]*inv, a0[3]*inv);
        float4 o1 = make_float4(a1[0]*inv, a1[1]*inv, a1[2]*inv, a1[3]*inv);
        float4 o2 = make_float4(a2[0]*inv, a2[1]*inv, a2[2]*inv, a2[3]*inv);
        *(float4*)(ob + 0 * HW) = o0;
        *(float4*)(ob + 1 * HW) = o1;
        *(float4*)(ob + 2 * HW) = o2;
    }
}

extern "C" void kernel_launch(void* const* d_in, const int* in_sizes, int n_in,
                              void* d_out, int out_size)
{
    const float* x    = (const float*)d_in[0];
    const float* kern = (const float*)d_in[1];
    // defensive: identify tensors by size (input = 393216, kernel = 47316992)
    if (n_in >= 2 && in_sizes[0] > in_sizes[1]) {
        const float* t = x; x = kern; kern = t;
    }

    cudaFuncSetAttribute(svblur_kernel,
                         cudaFuncAttributeMaxDynamicSharedMemorySize, SMEM_BYTES);

    dim3 grid(HGT / TI, 2);   // (128, 2) = 256 blocks, 16 warps each
    svblur_kernel<<<grid, NTHR, SMEM_BYTES>>>(x, kern, (float*)d_out);
}